// round 2
// baseline (speedup 1.0000x reference)
#include <cuda_runtime.h>
#include <cuda_bf16.h>
#include <stdint.h>

#define N_NODES 100000
#define N_EDGES 1600000
#define NUM_RELS 8
#define E_DIM 32
#define MAX_LEN 8
#define H_DIM 64
#define OUT_COLS 512          // NUM_RELS * H_DIM
#define NLDA 72               // padded smem leading dim (bf16 elems)

// ---------------- scratch (static device allocations; no cudaMalloc) -------------
__device__ float g_x[(size_t)N_NODES * H_DIM];            // 25.6 MB
__device__ float g_h[(size_t)N_NODES * H_DIM];            // 25.6 MB
__device__ float g_H[(size_t)NUM_RELS * N_NODES * H_DIM]; // 204.8 MB
__device__ int   g_cnt[N_NODES];
__device__ int   g_rowptr[N_NODES + 1];
__device__ int   g_wp[N_NODES];
__device__ int   g_bsum[128];
__device__ int   g_eoff[N_EDGES];    // etype*N + src  (sorted by dst)
__device__ float g_enorm[N_EDGES];   // norm            (sorted by dst)
__device__ float g_W1[H_DIM * OUT_COLS];
__device__ float g_W2[H_DIM * OUT_COLS];

// ---------------- CSR build ----------------
__global__ void k_zero_cnt() {
    int i = blockIdx.x * blockDim.x + threadIdx.x;
    if (i < N_NODES) g_cnt[i] = 0;
}

__global__ void k_hist(const int* __restrict__ dst) {
    int e = blockIdx.x * blockDim.x + threadIdx.x;
    if (e < N_EDGES) atomicAdd(&g_cnt[dst[e]], 1);
}

__global__ void k_scan_local() {   // 1024 threads/block, 98 blocks
    __shared__ int warpsums[32];
    int i = blockIdx.x * 1024 + threadIdx.x;
    int v = (i < N_NODES) ? g_cnt[i] : 0;
    int lane = threadIdx.x & 31, wid = threadIdx.x >> 5;
    int s = v;
    #pragma unroll
    for (int d = 1; d < 32; d <<= 1) {
        int t = __shfl_up_sync(0xFFFFFFFFu, s, d);
        if (lane >= d) s += t;
    }
    if (lane == 31) warpsums[wid] = s;
    __syncthreads();
    if (wid == 0) {
        int ws = warpsums[lane];
        #pragma unroll
        for (int d = 1; d < 32; d <<= 1) {
            int t = __shfl_up_sync(0xFFFFFFFFu, ws, d);
            if (lane >= d) ws += t;
        }
        warpsums[lane] = ws;
    }
    __syncthreads();
    int base = (wid > 0) ? warpsums[wid - 1] : 0;
    int incl = s + base;
    if (i < N_NODES) g_rowptr[i] = incl - v;             // local exclusive
    if (threadIdx.x == 1023) g_bsum[blockIdx.x] = incl;  // block total
}

__global__ void k_scan_bsums(int nb) {   // 1 block of 128
    __shared__ int sh[128];
    int t = threadIdx.x;
    int v = (t < nb) ? g_bsum[t] : 0;
    sh[t] = v;
    __syncthreads();
    for (int off = 1; off < 128; off <<= 1) {
        int add = (t >= off) ? sh[t - off] : 0;
        __syncthreads();
        sh[t] += add;
        __syncthreads();
    }
    if (t < nb) g_bsum[t] = sh[t] - v;   // exclusive
}

__global__ void k_scan_add() {
    int i = blockIdx.x * 1024 + threadIdx.x;
    if (i < N_NODES) {
        int val = g_rowptr[i] + g_bsum[blockIdx.x];
        g_rowptr[i] = val;
        g_wp[i] = val;
    }
    if (blockIdx.x == 0 && threadIdx.x == 0) g_rowptr[N_NODES] = N_EDGES;
}

__global__ void k_scatter(const int* __restrict__ src, const int* __restrict__ dst,
                          const int* __restrict__ etype, const float* __restrict__ norm) {
    int e = blockIdx.x * blockDim.x + threadIdx.x;
    if (e >= N_EDGES) return;
    int d = dst[e];
    int p = atomicAdd(&g_wp[d], 1);
    g_eoff[p] = etype[e] * N_NODES + src[e];
    g_enorm[p] = norm[e];
}

// ---------------- weight prep:  W[r] = sum_b comp[r,b] V[b]  -> [k=in][r*64+o] ------
__global__ void k_prepw(const float* __restrict__ V1, const float* __restrict__ c1,
                        const float* __restrict__ V2, const float* __restrict__ c2) {
    int t = blockIdx.x * blockDim.x + threadIdx.x;
    if (t >= 2 * H_DIM * OUT_COLS) return;
    int sel = t >= H_DIM * OUT_COLS;
    int u = t & (H_DIM * OUT_COLS - 1);
    int k = u >> 9;          // input dim
    int c = u & 511;         // r*64+o
    int r = c >> 6, o = c & 63;
    const float* V = sel ? V2 : V1;
    const float* cp = sel ? c2 : c1;
    float s = 0.f;
    #pragma unroll
    for (int b = 0; b < 8; b++)
        s += cp[r * 8 + b] * V[(b * 64 + k) * 64 + o];
    (sel ? g_W2 : g_W1)[u] = s;
}

// ---------------- mma helper ----------------
__device__ __forceinline__ void mma16816(float* c, const uint32_t* a, const uint32_t* b) {
    asm volatile(
        "mma.sync.aligned.m16n8k16.row.col.f32.bf16.bf16.f32 "
        "{%0,%1,%2,%3}, {%4,%5,%6,%7}, {%8,%9}, {%0,%1,%2,%3};\n"
        : "+f"(c[0]), "+f"(c[1]), "+f"(c[2]), "+f"(c[3])
        : "r"(a[0]), "r"(a[1]), "r"(a[2]), "r"(a[3]), "r"(b[0]), "r"(b[1]));
}

__device__ __forceinline__ void split_bf16(float v, __nv_bfloat16& hi, __nv_bfloat16& lo) {
    hi = __float2bfloat16(v);
    lo = __float2bfloat16(v - __bfloat162float(hi));
}

// ---------------- size matcher: g_x = gather(emb)[N,256] @ sm_w^T + sm_b -----------
// block: 128 rows x 64 cols, K=256 in 4 chunks of 64. 256 threads (8 warps, 2x4).
__global__ void k_sm(const int* __restrict__ feat, const float* __restrict__ emb,
                     const float* __restrict__ smw, const float* __restrict__ smb) {
    extern __shared__ char smraw[];
    __nv_bfloat16* Ahi = (__nv_bfloat16*)smraw;                 // 128*72
    __nv_bfloat16* Alo = Ahi + 128 * NLDA;
    __nv_bfloat16* Bhi = Alo + 128 * NLDA;                      // 64*72
    __nv_bfloat16* Blo = Bhi + 64 * NLDA;
    int* sfeat = (int*)(Blo + 64 * NLDA);                       // 128*8

    int tid = threadIdx.x;
    int rb = blockIdx.x * 128;

    for (int idx = tid; idx < 128 * 8; idx += 256) {
        int r = idx >> 3, j = idx & 7;
        sfeat[idx] = (rb + r < N_NODES) ? feat[(size_t)(rb + r) * 8 + j] : 0;
    }

    int lane = tid & 31, warp = tid >> 5;
    int wr = (warp >> 2) * 64;       // 0 or 64
    int wc = (warp & 3) * 16;        // 0,16,32,48
    int g = lane >> 2, t = lane & 3;

    float C[8][4];
    #pragma unroll
    for (int i = 0; i < 8; i++)
        #pragma unroll
        for (int j = 0; j < 4; j++) C[i][j] = 0.f;

    for (int kc = 0; kc < 4; kc++) {
        __syncthreads();
        for (int idx = tid; idx < 128 * 64; idx += 256) {
            int r = idx >> 6, k = idx & 63;
            float v = 0.f;
            if (rb + r < N_NODES) {
                int fid = sfeat[r * 8 + kc * 2 + (k >> 5)];
                v = emb[(size_t)fid * 32 + (k & 31)];
            }
            __nv_bfloat16 h, l; split_bf16(v, h, l);
            Ahi[r * NLDA + k] = h; Alo[r * NLDA + k] = l;
        }
        for (int idx = tid; idx < 64 * 64; idx += 256) {
            int n = idx >> 6, k = idx & 63;
            float v = smw[n * 256 + kc * 64 + k];
            __nv_bfloat16 h, l; split_bf16(v, h, l);
            Bhi[n * NLDA + k] = h; Blo[n * NLDA + k] = l;
        }
        __syncthreads();

        #pragma unroll
        for (int ks = 0; ks < 4; ks++) {
            int k0 = ks * 16;
            #pragma unroll
            for (int p = 0; p < 3; p++) {
                const __nv_bfloat16* As = (p == 1) ? Alo : Ahi;
                const __nv_bfloat16* Bs = (p == 2) ? Blo : Bhi;
                uint32_t a[4][4], b[2][2];
                #pragma unroll
                for (int mt = 0; mt < 4; mt++) {
                    int r0 = wr + mt * 16;
                    a[mt][0] = *(const uint32_t*)(As + (r0 + g) * NLDA + k0 + 2 * t);
                    a[mt][1] = *(const uint32_t*)(As + (r0 + g + 8) * NLDA + k0 + 2 * t);
                    a[mt][2] = *(const uint32_t*)(As + (r0 + g) * NLDA + k0 + 8 + 2 * t);
                    a[mt][3] = *(const uint32_t*)(As + (r0 + g + 8) * NLDA + k0 + 8 + 2 * t);
                }
                #pragma unroll
                for (int nt = 0; nt < 2; nt++) {
                    int c0 = wc + nt * 8 + g;
                    b[nt][0] = *(const uint32_t*)(Bs + c0 * NLDA + k0 + 2 * t);
                    b[nt][1] = *(const uint32_t*)(Bs + c0 * NLDA + k0 + 8 + 2 * t);
                }
                #pragma unroll
                for (int mt = 0; mt < 4; mt++)
                    #pragma unroll
                    for (int nt = 0; nt < 2; nt++)
                        mma16816(C[mt * 2 + nt], a[mt], b[nt]);
            }
        }
    }

    #pragma unroll
    for (int mt = 0; mt < 4; mt++) {
        int r0 = rb + wr + mt * 16 + g;
        int r1 = r0 + 8;
        #pragma unroll
        for (int nt = 0; nt < 2; nt++) {
            int gc = wc + nt * 8 + 2 * t;
            float b0 = smb[gc], b1 = smb[gc + 1];
            if (r0 < N_NODES)
                *(float2*)(g_x + (size_t)r0 * 64 + gc) =
                    make_float2(C[mt * 2 + nt][0] + b0, C[mt * 2 + nt][1] + b1);
            if (r1 < N_NODES)
                *(float2*)(g_x + (size_t)r1 * 64 + gc) =
                    make_float2(C[mt * 2 + nt][2] + b0, C[mt * 2 + nt][3] + b1);
        }
    }
}

// ---------------- relation GEMM: g_H[r][n][o] = X[n,:] @ W[:, r*64+o] ---------------
// phase 0: X=g_x, W=g_W1; phase 1: X=g_h, W=g_W2.  All buffers resolved device-side.
__global__ void k_relgemm(int phase) {
    const float* __restrict__ X = phase ? g_h : g_x;
    const float* __restrict__ W = phase ? g_W2 : g_W1;
    float* __restrict__ Hout = g_H;

    extern __shared__ char smraw[];
    __nv_bfloat16* Ahi = (__nv_bfloat16*)smraw;     // 128*72
    __nv_bfloat16* Alo = Ahi + 128 * NLDA;
    __nv_bfloat16* Bhi = Alo + 128 * NLDA;          // 128*72 (Bt: [col][k])
    __nv_bfloat16* Blo = Bhi + 128 * NLDA;

    int tid = threadIdx.x;
    int rb = blockIdx.x * 128;
    int cb = blockIdx.y * 128;

    for (int idx = tid; idx < 128 * 64; idx += 256) {
        int r = idx >> 6, k = idx & 63;
        float v = (rb + r < N_NODES) ? X[(size_t)(rb + r) * 64 + k] : 0.f;
        __nv_bfloat16 h, l; split_bf16(v, h, l);
        Ahi[r * NLDA + k] = h; Alo[r * NLDA + k] = l;
    }
    for (int idx = tid; idx < 128 * 64; idx += 256) {
        int k = idx >> 7, n = idx & 127;
        float v = W[k * OUT_COLS + cb + n];
        __nv_bfloat16 h, l; split_bf16(v, h, l);
        Bhi[n * NLDA + k] = h; Blo[n * NLDA + k] = l;
    }
    __syncthreads();

    int lane = tid & 31, warp = tid >> 5;
    int wr = (warp >> 2) * 64;
    int wc = (warp & 3) * 32;
    int g = lane >> 2, t = lane & 3;

    float C[16][4];
    #pragma unroll
    for (int i = 0; i < 16; i++)
        #pragma unroll
        for (int j = 0; j < 4; j++) C[i][j] = 0.f;

    #pragma unroll
    for (int ks = 0; ks < 4; ks++) {
        int k0 = ks * 16;
        #pragma unroll
        for (int p = 0; p < 3; p++) {
            const __nv_bfloat16* As = (p == 1) ? Alo : Ahi;
            const __nv_bfloat16* Bs = (p == 2) ? Blo : Bhi;
            uint32_t a[4][4], b[4][2];
            #pragma unroll
            for (int mt = 0; mt < 4; mt++) {
                int r0 = wr + mt * 16;
                a[mt][0] = *(const uint32_t*)(As + (r0 + g) * NLDA + k0 + 2 * t);
                a[mt][1] = *(const uint32_t*)(As + (r0 + g + 8) * NLDA + k0 + 2 * t);
                a[mt][2] = *(const uint32_t*)(As + (r0 + g) * NLDA + k0 + 8 + 2 * t);
                a[mt][3] = *(const uint32_t*)(As + (r0 + g + 8) * NLDA + k0 + 8 + 2 * t);
            }
            #pragma unroll
            for (int nt = 0; nt < 4; nt++) {
                int c0 = wc + nt * 8 + g;
                b[nt][0] = *(const uint32_t*)(Bs + c0 * NLDA + k0 + 2 * t);
                b[nt][1] = *(const uint32_t*)(Bs + c0 * NLDA + k0 + 8 + 2 * t);
            }
            #pragma unroll
            for (int mt = 0; mt < 4; mt++)
                #pragma unroll
                for (int nt = 0; nt < 4; nt++)
                    mma16816(C[mt * 4 + nt], a[mt], b[nt]);
        }
    }

    #pragma unroll
    for (int mt = 0; mt < 4; mt++) {
        int r0 = rb + wr + mt * 16 + g;
        int r1 = r0 + 8;
        #pragma unroll
        for (int nt = 0; nt < 4; nt++) {
            int gc = cb + wc + nt * 8 + 2 * t;
            int rel = gc >> 6, o = gc & 63;
            float* dstp = Hout + (size_t)rel * N_NODES * 64 + o;
            if (r0 < N_NODES)
                *(float2*)(dstp + (size_t)r0 * 64) = make_float2(C[mt * 4 + nt][0], C[mt * 4 + nt][1]);
            if (r1 < N_NODES)
                *(float2*)(dstp + (size_t)r1 * 64) = make_float2(C[mt * 4 + nt][2], C[mt * 4 + nt][3]);
        }
    }
}

// ---------------- edge aggregation: warp per node, CSR over dst ---------------------
// out == nullptr -> write g_h (layer 1, with relu). Otherwise write out (layer 2).
__global__ void k_edge(const float* __restrict__ bias, float* out, int dorelu) {
    float* __restrict__ op = out ? out : g_h;
    const float* __restrict__ Hbuf = g_H;
    int node = blockIdx.x * 8 + (threadIdx.x >> 5);
    int lane = threadIdx.x & 31;
    if (node >= N_NODES) return;
    int beg = g_rowptr[node], end = g_rowptr[node + 1];
    int c = lane * 2;
    float ax = 0.f, ay = 0.f;
    int e = beg;
    for (; e + 4 <= end; e += 4) {
        int o0 = g_eoff[e], o1 = g_eoff[e + 1], o2 = g_eoff[e + 2], o3 = g_eoff[e + 3];
        float n0 = g_enorm[e], n1 = g_enorm[e + 1], n2 = g_enorm[e + 2], n3 = g_enorm[e + 3];
        float2 v0 = *(const float2*)(Hbuf + (size_t)o0 * 64 + c);
        float2 v1 = *(const float2*)(Hbuf + (size_t)o1 * 64 + c);
        float2 v2 = *(const float2*)(Hbuf + (size_t)o2 * 64 + c);
        float2 v3 = *(const float2*)(Hbuf + (size_t)o3 * 64 + c);
        ax = fmaf(n0, v0.x, ax); ay = fmaf(n0, v0.y, ay);
        ax = fmaf(n1, v1.x, ax); ay = fmaf(n1, v1.y, ay);
        ax = fmaf(n2, v2.x, ax); ay = fmaf(n2, v2.y, ay);
        ax = fmaf(n3, v3.x, ax); ay = fmaf(n3, v3.y, ay);
    }
    for (; e < end; e++) {
        int o0 = g_eoff[e];
        float n0 = g_enorm[e];
        float2 v0 = *(const float2*)(Hbuf + (size_t)o0 * 64 + c);
        ax = fmaf(n0, v0.x, ax); ay = fmaf(n0, v0.y, ay);
    }
    ax += bias[c]; ay += bias[c + 1];
    if (dorelu) { ax = fmaxf(ax, 0.f); ay = fmaxf(ay, 0.f); }
    *(float2*)(op + (size_t)node * 64 + c) = make_float2(ax, ay);
}

// ---------------- launch ----------------
extern "C" void kernel_launch(void* const* d_in, const int* in_sizes, int n_in,
                              void* d_out, int out_size) {
    const int* feat = (const int*)d_in[0];
    const int* src = (const int*)d_in[1];
    const int* dst = (const int*)d_in[2];
    const int* etype = (const int*)d_in[3];
    const float* norm = (const float*)d_in[4];
    const float* emb = (const float*)d_in[5];
    const float* smw = (const float*)d_in[6];
    const float* smb = (const float*)d_in[7];
    const float* V1 = (const float*)d_in[8];
    const float* c1 = (const float*)d_in[9];
    const float* b1 = (const float*)d_in[10];
    const float* V2 = (const float*)d_in[11];
    const float* c2 = (const float*)d_in[12];
    const float* b2 = (const float*)d_in[13];
    float* out = (float*)d_out;

    const int smemSM = (128 * NLDA * 2 + 64 * NLDA * 2) * 2 + 128 * 8 * 4;
    const int smemRG = (128 * NLDA * 2) * 4;                                  // 73728
    static int attr_done = 0;
    if (!attr_done) {
        cudaFuncSetAttribute(k_sm, cudaFuncAttributeMaxDynamicSharedMemorySize, smemSM);
        cudaFuncSetAttribute(k_relgemm, cudaFuncAttributeMaxDynamicSharedMemorySize, smemRG);
        attr_done = 1;
    }

    // CSR build (shared by both layers)
    k_zero_cnt<<<(N_NODES + 255) / 256, 256>>>();
    k_hist<<<N_EDGES / 256, 256>>>(dst);
    int nscan = (N_NODES + 1023) / 1024;   // 98
    k_scan_local<<<nscan, 1024>>>();
    k_scan_bsums<<<1, 128>>>(nscan);
    k_scan_add<<<nscan, 1024>>>();
    k_scatter<<<N_EDGES / 256, 256>>>(src, dst, etype, norm);

    // weights
    k_prepw<<<(2 * H_DIM * OUT_COLS) / 256, 256>>>(V1, c1, V2, c2);

    // size matcher -> g_x
    k_sm<<<(N_NODES + 127) / 128, 256, smemSM>>>(feat, emb, smw, smb);

    // layer 1
    k_relgemm<<<dim3((N_NODES + 127) / 128, 4), 256, smemRG>>>(0);
    k_edge<<<(N_NODES + 7) / 8, 256>>>(b1, nullptr, 1);

    // layer 2
    k_relgemm<<<dim3((N_NODES + 127) / 128, 4), 256, smemRG>>>(1);
    k_edge<<<(N_NODES + 7) / 8, 256>>>(b2, out, 0);
}